// round 12
// baseline (speedup 1.0000x reference)
#include <cuda_runtime.h>
#include <stdint.h>

#define N_NODES 100000
#define D_FEAT  128
#define E_EDGES 1600000

// Scratch: per-relation aggregation buffers + degree counters.
// __device__ globals (no allocation allowed in kernel_launch).
__device__ float g_agg[2ull * N_NODES * D_FEAT];   // 102.4 MB
__device__ int   g_deg[2 * N_NODES];

// ---------------------------------------------------------------------------
// Zero scratch
// ---------------------------------------------------------------------------
__global__ void zero_kernel() {
    const size_t total4 = (2ull * N_NODES * D_FEAT) / 4;
    float4* p = reinterpret_cast<float4*>(g_agg);
    size_t stride = (size_t)gridDim.x * blockDim.x;
    for (size_t i = (size_t)blockIdx.x * blockDim.x + threadIdx.x; i < total4; i += stride)
        p[i] = make_float4(0.f, 0.f, 0.f, 0.f);
    const int ndeg = 2 * N_NODES;
    for (int i = blockIdx.x * blockDim.x + threadIdx.x; i < ndeg; i += gridDim.x * blockDim.x)
        g_deg[i] = 0;
}

// ---------------------------------------------------------------------------
// Scatter-aggregate: one warp per (relation, edge).
// Gather 512B row of x[src] coalesced (32 lanes x float4),
// vector reduction into g_agg[rel][dst] via red.global.add.v4.f32 (sm_90+).
// ---------------------------------------------------------------------------
__global__ __launch_bounds__(256) void scatter_kernel(
    const float* __restrict__ x,
    const int* __restrict__ src_f, const int* __restrict__ dst_f,
    const int* __restrict__ src_b, const int* __restrict__ dst_b)
{
    const int warp_global = (blockIdx.x * blockDim.x + threadIdx.x) >> 5;
    const int lane = threadIdx.x & 31;
    if (warp_global >= 2 * E_EDGES) return;

    const int rel = (warp_global >= E_EDGES) ? 1 : 0;
    const int e   = warp_global - rel * E_EDGES;
    const int* __restrict__ srcA = rel ? src_b : src_f;
    const int* __restrict__ dstA = rel ? dst_b : dst_f;

    const int s = __ldg(srcA + e);
    const int d = __ldg(dstA + e);

    const float4 v = reinterpret_cast<const float4*>(x + (size_t)s * D_FEAT)[lane];

    float* out = g_agg + ((size_t)rel * N_NODES + d) * D_FEAT + lane * 4;
    asm volatile("red.global.add.v4.f32 [%0], {%1,%2,%3,%4};"
                 :: "l"(out), "f"(v.x), "f"(v.y), "f"(v.z), "f"(v.w)
                 : "memory");

    if (lane == 0)
        atomicAdd(&g_deg[rel * N_NODES + d], 1);
}

// ---------------------------------------------------------------------------
// Fused GEMM: out = relu( [agg0/deg0 | agg1/deg1 | x] @ [W0 ; W1 ; L] + bias )
// A is logically [N, 384] (normalization fused into the A-tile load),
// B is [384, 128], C is [N, 128].
// 128x128 block tile, BK=16, 256 threads, 8x8 microtile.
// ---------------------------------------------------------------------------
#define BM 128
#define BN 128
#define BK 16

__global__ __launch_bounds__(256) void gemm_kernel(
    const float* __restrict__ x,
    const float* __restrict__ relw,    // [2,128,128] -> rows k in [0,256)
    const float* __restrict__ loopw,   // [128,128]   -> rows k in [256,384)
    const float* __restrict__ bias,    // [128]
    float* __restrict__ out)
{
    __shared__ float As[BK][BM + 4];   // transposed A tile (pad keeps 16B align: 132*4=528)
    __shared__ float Bs[BK][BN];

    const int tid = threadIdx.x;
    const int tx = tid & 15;           // 0..15  (column group, 8 cols each)
    const int ty = tid >> 4;           // 0..15  (row group, 8 rows each)
    const int block_row = blockIdx.x * BM;

    float acc[8][8];
    #pragma unroll
    for (int i = 0; i < 8; i++)
        #pragma unroll
        for (int j = 0; j < 8; j++)
            acc[i][j] = 0.f;

    for (int k0 = 0; k0 < 384; k0 += BK) {
        const int region = k0 >> 7;    // 0: agg_fwd, 1: agg_bwd, 2: x (BK=16 tiles never straddle)
        const int kk0 = k0 & 127;

        // ---- Load A tile: 128 rows x 16 cols = 512 float4, 2 per thread ----
        #pragma unroll
        for (int l = 0; l < 2; l++) {
            const int idx = tid + l * 256;
            const int row = idx >> 2;          // 0..127
            const int c4  = idx & 3;           // float4 col within BK
            const int n = block_row + row;
            float4 v = make_float4(0.f, 0.f, 0.f, 0.f);
            if (n < N_NODES) {
                if (region < 2) {
                    const float* base =
                        g_agg + ((size_t)region * N_NODES + n) * D_FEAT + kk0 + c4 * 4;
                    v = *reinterpret_cast<const float4*>(base);
                    const int dg = g_deg[region * N_NODES + n];
                    const float inv = 1.0f / (float)(dg > 1 ? dg : 1);
                    v.x *= inv; v.y *= inv; v.z *= inv; v.w *= inv;
                } else {
                    v = *reinterpret_cast<const float4*>(
                        x + (size_t)n * D_FEAT + kk0 + c4 * 4);
                }
            }
            const int kb = c4 * 4;
            As[kb + 0][row] = v.x;
            As[kb + 1][row] = v.y;
            As[kb + 2][row] = v.z;
            As[kb + 3][row] = v.w;
        }

        // ---- Load B tile: 16 rows x 128 cols = 512 float4, 2 per thread ----
        #pragma unroll
        for (int l = 0; l < 2; l++) {
            const int idx = tid + l * 256;
            const int brow = idx >> 5;         // 0..15
            const int bc4  = idx & 31;         // float4 col 0..31
            const int k = k0 + brow;
            const float* src = (k < 256)
                ? (relw + (size_t)k * D_FEAT + bc4 * 4)
                : (loopw + (size_t)(k - 256) * D_FEAT + bc4 * 4);
            *reinterpret_cast<float4*>(&Bs[brow][bc4 * 4]) =
                *reinterpret_cast<const float4*>(src);
        }

        __syncthreads();

        #pragma unroll
        for (int kk = 0; kk < BK; kk++) {
            float a[8], b[8];
            *reinterpret_cast<float4*>(&a[0]) =
                *reinterpret_cast<const float4*>(&As[kk][ty * 8]);
            *reinterpret_cast<float4*>(&a[4]) =
                *reinterpret_cast<const float4*>(&As[kk][ty * 8 + 4]);
            *reinterpret_cast<float4*>(&b[0]) =
                *reinterpret_cast<const float4*>(&Bs[kk][tx * 8]);
            *reinterpret_cast<float4*>(&b[4]) =
                *reinterpret_cast<const float4*>(&Bs[kk][tx * 8 + 4]);
            #pragma unroll
            for (int i = 0; i < 8; i++)
                #pragma unroll
                for (int j = 0; j < 8; j++)
                    acc[i][j] = fmaf(a[i], b[j], acc[i][j]);
        }

        __syncthreads();
    }

    // ---- Epilogue: + bias, relu, store ----
    #pragma unroll
    for (int i = 0; i < 8; i++) {
        const int n = block_row + ty * 8 + i;
        if (n >= N_NODES) break;
        #pragma unroll
        for (int j4 = 0; j4 < 2; j4++) {
            const int col = tx * 8 + j4 * 4;
            const float4 bv = *reinterpret_cast<const float4*>(bias + col);
            float4 r;
            r.x = fmaxf(acc[i][j4 * 4 + 0] + bv.x, 0.f);
            r.y = fmaxf(acc[i][j4 * 4 + 1] + bv.y, 0.f);
            r.z = fmaxf(acc[i][j4 * 4 + 2] + bv.z, 0.f);
            r.w = fmaxf(acc[i][j4 * 4 + 3] + bv.w, 0.f);
            *reinterpret_cast<float4*>(out + (size_t)n * D_FEAT + col) = r;
        }
    }
}

// ---------------------------------------------------------------------------
// Launch
// ---------------------------------------------------------------------------
extern "C" void kernel_launch(void* const* d_in, const int* in_sizes, int n_in,
                              void* d_out, int out_size)
{
    const float* x       = (const float*)d_in[0];
    const int*   src_fwd = (const int*)  d_in[1];
    const int*   dst_fwd = (const int*)  d_in[2];
    const int*   src_bwd = (const int*)  d_in[3];
    const int*   dst_bwd = (const int*)  d_in[4];
    const float* rel_w   = (const float*)d_in[5];
    const float* loop_w  = (const float*)d_in[6];
    const float* h_bias  = (const float*)d_in[7];
    float* out = (float*)d_out;

    // 1) zero scratch (agg + deg)
    zero_kernel<<<2048, 256>>>();

    // 2) scatter-aggregate: one warp per (relation, edge)
    const long long total_warps = 2LL * E_EDGES;
    const int warps_per_block = 256 / 32;
    const int nblocks = (int)((total_warps + warps_per_block - 1) / warps_per_block);
    scatter_kernel<<<nblocks, 256>>>(x, src_fwd, dst_fwd, src_bwd, dst_bwd);

    // 3) fused normalize + GEMM + bias + relu
    const int gemm_blocks = (N_NODES + BM - 1) / BM;
    gemm_kernel<<<gemm_blocks, 256>>>(x, rel_w, loop_w, h_bias, out);
}

// round 13
// speedup vs baseline: 1.1705x; 1.1705x over previous
#include <cuda_runtime.h>
#include <stdint.h>

#define N_NODES   100000
#define D_FEAT    128
#define E_EDGES   1600000
#define NUM_PARTS 4
#define PART_SIZE (N_NODES / NUM_PARTS)   // 25000
#define CHUNKS_PER_REL (E_EDGES / 32)     // 50000 (E divisible by 32)

// Scratch: per-relation aggregation buffers + degree counters.
__device__ float g_agg[2ull * N_NODES * D_FEAT];   // 102.4 MB
__device__ int   g_deg[2 * N_NODES];

// ---------------------------------------------------------------------------
// Zero scratch
// ---------------------------------------------------------------------------
__global__ void zero_kernel() {
    const size_t total4 = (2ull * N_NODES * D_FEAT) / 4;
    float4* p = reinterpret_cast<float4*>(g_agg);
    size_t stride = (size_t)gridDim.x * blockDim.x;
    for (size_t i = (size_t)blockIdx.x * blockDim.x + threadIdx.x; i < total4; i += stride)
        p[i] = make_float4(0.f, 0.f, 0.f, 0.f);
    const int ndeg = 2 * N_NODES;
    for (int i = blockIdx.x * blockDim.x + threadIdx.x; i < ndeg; i += gridDim.x * blockDim.x)
        g_deg[i] = 0;
}

// ---------------------------------------------------------------------------
// Partitioned scatter-aggregate pass.
// Each warp owns 32 consecutive edges of one relation. Lanes load the 32 dst
// ids; edges whose dst lies in [part*PART_SIZE, (part+1)*PART_SIZE) are
// processed one-by-one with the FULL warp doing the 512B gather + red.v4.
// Per pass, the live agg slice (2 x 12.8MB) + x (51MB) stay L2-resident,
// so reds never touch DRAM.
// ---------------------------------------------------------------------------
__global__ __launch_bounds__(256) void scatter_pass_kernel(
    const float* __restrict__ x,
    const int* __restrict__ src_f, const int* __restrict__ dst_f,
    const int* __restrict__ src_b, const int* __restrict__ dst_b,
    int part)
{
    const int chunk = (blockIdx.x * blockDim.x + threadIdx.x) >> 5;
    const int lane  = threadIdx.x & 31;
    if (chunk >= 2 * CHUNKS_PER_REL) return;

    const int rel  = (chunk >= CHUNKS_PER_REL) ? 1 : 0;
    const int base = (chunk - rel * CHUNKS_PER_REL) * 32;
    const int* __restrict__ srcA = rel ? src_b : src_f;
    const int* __restrict__ dstA = rel ? dst_b : dst_f;

    const int lo = part * PART_SIZE;
    const int hi = lo + PART_SIZE;

    const int e = base + lane;
    const int d = __ldg(dstA + e);
    const bool in = (d >= lo) && (d < hi);

    unsigned mask = __ballot_sync(0xffffffffu, in);
    if (mask == 0) return;

    int s = 0;
    if (in) {
        s = __ldg(srcA + e);
        atomicAdd(&g_deg[rel * N_NODES + d], 1);
    }

    const size_t rel_off = (size_t)rel * N_NODES;

    while (mask) {
        const int i = __ffs(mask) - 1;
        mask &= mask - 1;
        const int si = __shfl_sync(0xffffffffu, s, i);
        const int di = __shfl_sync(0xffffffffu, d, i);

        const float4 v =
            reinterpret_cast<const float4*>(x + (size_t)si * D_FEAT)[lane];

        float* outp = g_agg + (rel_off + di) * D_FEAT + lane * 4;
        asm volatile("red.global.add.v4.f32 [%0], {%1,%2,%3,%4};"
                     :: "l"(outp), "f"(v.x), "f"(v.y), "f"(v.z), "f"(v.w)
                     : "memory");
    }
}

// ---------------------------------------------------------------------------
// Fused GEMM: out = relu( [agg0/deg0 | agg1/deg1 | x] @ [W0 ; W1 ; L] + bias )
// 128x128 block tile, BK=16, 256 threads, 8x8 microtile. (unchanged)
// ---------------------------------------------------------------------------
#define BM 128
#define BN 128
#define BK 16

__global__ __launch_bounds__(256) void gemm_kernel(
    const float* __restrict__ x,
    const float* __restrict__ relw,    // [2,128,128] -> rows k in [0,256)
    const float* __restrict__ loopw,   // [128,128]   -> rows k in [256,384)
    const float* __restrict__ bias,    // [128]
    float* __restrict__ out)
{
    __shared__ float As[BK][BM + 4];
    __shared__ float Bs[BK][BN];

    const int tid = threadIdx.x;
    const int tx = tid & 15;
    const int ty = tid >> 4;
    const int block_row = blockIdx.x * BM;

    float acc[8][8];
    #pragma unroll
    for (int i = 0; i < 8; i++)
        #pragma unroll
        for (int j = 0; j < 8; j++)
            acc[i][j] = 0.f;

    for (int k0 = 0; k0 < 384; k0 += BK) {
        const int region = k0 >> 7;
        const int kk0 = k0 & 127;

        #pragma unroll
        for (int l = 0; l < 2; l++) {
            const int idx = tid + l * 256;
            const int row = idx >> 2;
            const int c4  = idx & 3;
            const int n = block_row + row;
            float4 v = make_float4(0.f, 0.f, 0.f, 0.f);
            if (n < N_NODES) {
                if (region < 2) {
                    const float* base =
                        g_agg + ((size_t)region * N_NODES + n) * D_FEAT + kk0 + c4 * 4;
                    v = *reinterpret_cast<const float4*>(base);
                    const int dg = g_deg[region * N_NODES + n];
                    const float inv = 1.0f / (float)(dg > 1 ? dg : 1);
                    v.x *= inv; v.y *= inv; v.z *= inv; v.w *= inv;
                } else {
                    v = *reinterpret_cast<const float4*>(
                        x + (size_t)n * D_FEAT + kk0 + c4 * 4);
                }
            }
            const int kb = c4 * 4;
            As[kb + 0][row] = v.x;
            As[kb + 1][row] = v.y;
            As[kb + 2][row] = v.z;
            As[kb + 3][row] = v.w;
        }

        #pragma unroll
        for (int l = 0; l < 2; l++) {
            const int idx = tid + l * 256;
            const int brow = idx >> 5;
            const int bc4  = idx & 31;
            const int k = k0 + brow;
            const float* src = (k < 256)
                ? (relw + (size_t)k * D_FEAT + bc4 * 4)
                : (loopw + (size_t)(k - 256) * D_FEAT + bc4 * 4);
            *reinterpret_cast<float4*>(&Bs[brow][bc4 * 4]) =
                *reinterpret_cast<const float4*>(src);
        }

        __syncthreads();

        #pragma unroll
        for (int kk = 0; kk < BK; kk++) {
            float a[8], b[8];
            *reinterpret_cast<float4*>(&a[0]) =
                *reinterpret_cast<const float4*>(&As[kk][ty * 8]);
            *reinterpret_cast<float4*>(&a[4]) =
                *reinterpret_cast<const float4*>(&As[kk][ty * 8 + 4]);
            *reinterpret_cast<float4*>(&b[0]) =
                *reinterpret_cast<const float4*>(&Bs[kk][tx * 8]);
            *reinterpret_cast<float4*>(&b[4]) =
                *reinterpret_cast<const float4*>(&Bs[kk][tx * 8 + 4]);
            #pragma unroll
            for (int i = 0; i < 8; i++)
                #pragma unroll
                for (int j = 0; j < 8; j++)
                    acc[i][j] = fmaf(a[i], b[j], acc[i][j]);
        }

        __syncthreads();
    }

    #pragma unroll
    for (int i = 0; i < 8; i++) {
        const int n = block_row + ty * 8 + i;
        if (n >= N_NODES) break;
        #pragma unroll
        for (int j4 = 0; j4 < 2; j4++) {
            const int col = tx * 8 + j4 * 4;
            const float4 bv = *reinterpret_cast<const float4*>(bias + col);
            float4 r;
            r.x = fmaxf(acc[i][j4 * 4 + 0] + bv.x, 0.f);
            r.y = fmaxf(acc[i][j4 * 4 + 1] + bv.y, 0.f);
            r.z = fmaxf(acc[i][j4 * 4 + 2] + bv.z, 0.f);
            r.w = fmaxf(acc[i][j4 * 4 + 3] + bv.w, 0.f);
            *reinterpret_cast<float4*>(out + (size_t)n * D_FEAT + col) = r;
        }
    }
}

// ---------------------------------------------------------------------------
// Launch
// ---------------------------------------------------------------------------
extern "C" void kernel_launch(void* const* d_in, const int* in_sizes, int n_in,
                              void* d_out, int out_size)
{
    const float* x       = (const float*)d_in[0];
    const int*   src_fwd = (const int*)  d_in[1];
    const int*   dst_fwd = (const int*)  d_in[2];
    const int*   src_bwd = (const int*)  d_in[3];
    const int*   dst_bwd = (const int*)  d_in[4];
    const float* rel_w   = (const float*)d_in[5];
    const float* loop_w  = (const float*)d_in[6];
    const float* h_bias  = (const float*)d_in[7];
    float* out = (float*)d_out;

    // 1) zero scratch (agg + deg)
    zero_kernel<<<2048, 256>>>();

    // 2) partitioned scatter-aggregate: 4 dst-range passes, each L2-resident
    const int total_chunks = 2 * CHUNKS_PER_REL;           // 100000 warps
    const int nblocks = (total_chunks * 32 + 255) / 256;   // 12500 blocks
    for (int part = 0; part < NUM_PARTS; part++) {
        scatter_pass_kernel<<<nblocks, 256>>>(
            x, src_fwd, dst_fwd, src_bwd, dst_bwd, part);
    }

    // 3) fused normalize + GEMM + bias + relu
    const int gemm_blocks = (N_NODES + BM - 1) / BM;
    gemm_kernel<<<gemm_blocks, 256>>>(x, rel_w, loop_w, h_bias, out);
}

// round 14
// speedup vs baseline: 1.6605x; 1.4186x over previous
#include <cuda_runtime.h>
#include <stdint.h>

#define N_NODES   100000
#define D_FEAT    128
#define E_EDGES   1600000
#define SEG       (2 * N_NODES)        // 200000 (rel,node) buckets
#define SCAN_BLK  196                  // 196 * 1024 >= SEG

// Scratch (__device__ globals — no allocation allowed)
__device__ float g_agg[(size_t)SEG * D_FEAT];     // 102.4 MB
__device__ int   g_deg[SEG];
__device__ int   g_offs[SEG];
__device__ int   g_cursor[SEG];
__device__ int   g_bsum[SCAN_BLK];
__device__ int   g_sorted_src[2 * E_EDGES];       // 12.8 MB

// ---------------------------------------------------------------------------
// 1) zero degree histogram
// ---------------------------------------------------------------------------
__global__ void init_deg_kernel() {
    int i = blockIdx.x * blockDim.x + threadIdx.x;
    if (i < SEG) g_deg[i] = 0;
}

// ---------------------------------------------------------------------------
// 2) degree histogram (RED to L2-resident 800KB)
// ---------------------------------------------------------------------------
__global__ __launch_bounds__(256) void hist_kernel(
    const int* __restrict__ dst_f, const int* __restrict__ dst_b)
{
    int idx = blockIdx.x * blockDim.x + threadIdx.x;
    if (idx >= 2 * E_EDGES) return;
    int rel = (idx >= E_EDGES) ? 1 : 0;
    int e = idx - rel * E_EDGES;
    int d = __ldg(rel ? dst_b + e : dst_f + e);
    atomicAdd(&g_deg[rel * N_NODES + d], 1);
}

// ---------------------------------------------------------------------------
// 3) exclusive scan of g_deg -> g_offs (3-kernel scan)
// ---------------------------------------------------------------------------
__global__ __launch_bounds__(256) void scan1_kernel() {
    const int base = blockIdx.x * 1024;
    const int tid  = threadIdx.x;
    const int lane = tid & 31, w = tid >> 5;

    int v[4], sum = 0;
    #pragma unroll
    for (int j = 0; j < 4; j++) {
        int idx = base + tid * 4 + j;
        v[j] = (idx < SEG) ? g_deg[idx] : 0;
        sum += v[j];
    }
    // warp inclusive scan of per-thread sums
    int inc = sum;
    #pragma unroll
    for (int d = 1; d < 32; d <<= 1) {
        int t = __shfl_up_sync(0xffffffffu, inc, d);
        if (lane >= d) inc += t;
    }
    __shared__ int wsum[8];
    if (lane == 31) wsum[w] = inc;
    __syncthreads();
    if (w == 0 && lane < 8) {
        int t = wsum[lane];
        int s = t;
        #pragma unroll
        for (int d = 1; d < 8; d <<= 1) {
            int u = __shfl_up_sync(0xffu, s, d);
            if (lane >= d) s += u;
        }
        wsum[lane] = s - t;   // exclusive warp offsets
    }
    __syncthreads();
    int excl = (inc - sum) + wsum[w];
    int run = excl;
    #pragma unroll
    for (int j = 0; j < 4; j++) {
        int idx = base + tid * 4 + j;
        if (idx < SEG) g_offs[idx] = run;
        run += v[j];
    }
    if (tid == 255) g_bsum[blockIdx.x] = excl + sum;  // block total
}

__global__ __launch_bounds__(256) void scan2_kernel() {
    const int tid = threadIdx.x;
    const int lane = tid & 31, w = tid >> 5;
    int v = (tid < SCAN_BLK) ? g_bsum[tid] : 0;
    int inc = v;
    #pragma unroll
    for (int d = 1; d < 32; d <<= 1) {
        int t = __shfl_up_sync(0xffffffffu, inc, d);
        if (lane >= d) inc += t;
    }
    __shared__ int wsum[8];
    if (lane == 31) wsum[w] = inc;
    __syncthreads();
    if (w == 0 && lane < 8) {
        int t = wsum[lane];
        int s = t;
        #pragma unroll
        for (int d = 1; d < 8; d <<= 1) {
            int u = __shfl_up_sync(0xffu, s, d);
            if (lane >= d) s += u;
        }
        wsum[lane] = s - t;
    }
    __syncthreads();
    if (tid < SCAN_BLK) g_bsum[tid] = (inc - v) + wsum[w];
}

__global__ __launch_bounds__(256) void scan3_kernel() {
    const int base = blockIdx.x * 1024;
    const int add = g_bsum[blockIdx.x];
    #pragma unroll
    for (int j = 0; j < 4; j++) {
        int idx = base + threadIdx.x * 4 + j;
        if (idx < SEG) {
            int o = g_offs[idx] + add;
            g_offs[idx] = o;
            g_cursor[idx] = o;
        }
    }
}

// ---------------------------------------------------------------------------
// 4) counting-sort fill: sorted_src grouped by (rel,dst)
// ---------------------------------------------------------------------------
__global__ __launch_bounds__(256) void fill_kernel(
    const int* __restrict__ src_f, const int* __restrict__ dst_f,
    const int* __restrict__ src_b, const int* __restrict__ dst_b)
{
    int idx = blockIdx.x * blockDim.x + threadIdx.x;
    if (idx >= 2 * E_EDGES) return;
    int rel = (idx >= E_EDGES) ? 1 : 0;
    int e = idx - rel * E_EDGES;
    int d = __ldg(rel ? dst_b + e : dst_f + e);
    int s = __ldg(rel ? src_b + e : src_f + e);
    int pos = atomicAdd(&g_cursor[rel * N_NODES + d], 1);
    g_sorted_src[pos] = s;
}

// ---------------------------------------------------------------------------
// 5) gather-aggregate: one warp per (rel,node). Accumulate in registers,
//    normalize by 1/max(deg,1), write the 512B agg row exactly once.
// ---------------------------------------------------------------------------
__global__ __launch_bounds__(256) void aggregate_kernel(
    const float* __restrict__ x)
{
    const int wi = (blockIdx.x * blockDim.x + threadIdx.x) >> 5;   // bucket
    const int lane = threadIdx.x & 31;
    if (wi >= SEG) return;

    const int beg = g_offs[wi];
    const int dg  = g_deg[wi];

    float4 acc0 = make_float4(0.f, 0.f, 0.f, 0.f);
    float4 acc1 = make_float4(0.f, 0.f, 0.f, 0.f);

    for (int k0 = 0; k0 < dg; k0 += 32) {
        const int cnt = min(32, dg - k0);
        const int sid = (lane < cnt) ? __ldg(g_sorted_src + beg + k0 + lane) : 0;
        int j = 0;
        for (; j + 1 < cnt; j += 2) {
            const int s0 = __shfl_sync(0xffffffffu, sid, j);
            const int s1 = __shfl_sync(0xffffffffu, sid, j + 1);
            const float4 v0 = __ldg(reinterpret_cast<const float4*>(
                x + (size_t)s0 * D_FEAT) + lane);
            const float4 v1 = __ldg(reinterpret_cast<const float4*>(
                x + (size_t)s1 * D_FEAT) + lane);
            acc0.x += v0.x; acc0.y += v0.y; acc0.z += v0.z; acc0.w += v0.w;
            acc1.x += v1.x; acc1.y += v1.y; acc1.z += v1.z; acc1.w += v1.w;
        }
        if (j < cnt) {
            const int s0 = __shfl_sync(0xffffffffu, sid, j);
            const float4 v0 = __ldg(reinterpret_cast<const float4*>(
                x + (size_t)s0 * D_FEAT) + lane);
            acc0.x += v0.x; acc0.y += v0.y; acc0.z += v0.z; acc0.w += v0.w;
        }
    }

    const float inv = 1.0f / (float)(dg > 1 ? dg : 1);
    float4 r;
    r.x = (acc0.x + acc1.x) * inv;
    r.y = (acc0.y + acc1.y) * inv;
    r.z = (acc0.z + acc1.z) * inv;
    r.w = (acc0.w + acc1.w) * inv;
    reinterpret_cast<float4*>(g_agg + (size_t)wi * D_FEAT)[lane] = r;
}

// ---------------------------------------------------------------------------
// 6) Fused GEMM with packed fp32x2 FMA (fma.rn.f32x2 — 2x fp32 throughput):
//    out = relu( [agg0 | agg1 | x] @ [W0 ; W1 ; L] + bias )
// ---------------------------------------------------------------------------
#define BM 128
#define BN 128
#define BK 16

__global__ __launch_bounds__(256) void gemm_kernel(
    const float* __restrict__ x,
    const float* __restrict__ relw,    // [2,128,128]
    const float* __restrict__ loopw,   // [128,128]
    const float* __restrict__ bias,    // [128]
    float* __restrict__ out)
{
    __shared__ float As[BK][BM + 4];
    __shared__ float Bs[BK][BN];

    const int tid = threadIdx.x;
    const int tx = tid & 15;
    const int ty = tid >> 4;
    const int block_row = blockIdx.x * BM;

    unsigned long long acc2[8][4];
    #pragma unroll
    for (int i = 0; i < 8; i++)
        #pragma unroll
        for (int j = 0; j < 4; j++)
            acc2[i][j] = 0ull;

    for (int k0 = 0; k0 < 384; k0 += BK) {
        const int region = k0 >> 7;
        const int kk0 = k0 & 127;

        // ---- A tile (agg already normalized) ----
        #pragma unroll
        for (int l = 0; l < 2; l++) {
            const int idx = tid + l * 256;
            const int row = idx >> 2;
            const int c4  = idx & 3;
            const int n = block_row + row;
            float4 v = make_float4(0.f, 0.f, 0.f, 0.f);
            if (n < N_NODES) {
                const float* base = (region < 2)
                    ? (g_agg + ((size_t)region * N_NODES + n) * D_FEAT + kk0 + c4 * 4)
                    : (x + (size_t)n * D_FEAT + kk0 + c4 * 4);
                v = *reinterpret_cast<const float4*>(base);
            }
            const int kb = c4 * 4;
            As[kb + 0][row] = v.x;
            As[kb + 1][row] = v.y;
            As[kb + 2][row] = v.z;
            As[kb + 3][row] = v.w;
        }

        // ---- B tile ----
        #pragma unroll
        for (int l = 0; l < 2; l++) {
            const int idx = tid + l * 256;
            const int brow = idx >> 5;
            const int bc4  = idx & 31;
            const int k = k0 + brow;
            const float* src = (k < 256)
                ? (relw + (size_t)k * D_FEAT + bc4 * 4)
                : (loopw + (size_t)(k - 256) * D_FEAT + bc4 * 4);
            *reinterpret_cast<float4*>(&Bs[brow][bc4 * 4]) =
                *reinterpret_cast<const float4*>(src);
        }

        __syncthreads();

        #pragma unroll
        for (int kk = 0; kk < BK; kk++) {
            float a[8];
            *reinterpret_cast<float4*>(&a[0]) =
                *reinterpret_cast<const float4*>(&As[kk][ty * 8]);
            *reinterpret_cast<float4*>(&a[4]) =
                *reinterpret_cast<const float4*>(&As[kk][ty * 8 + 4]);
            unsigned long long bb[4];
            bb[0] = *reinterpret_cast<const unsigned long long*>(&Bs[kk][tx * 8 + 0]);
            bb[1] = *reinterpret_cast<const unsigned long long*>(&Bs[kk][tx * 8 + 2]);
            bb[2] = *reinterpret_cast<const unsigned long long*>(&Bs[kk][tx * 8 + 4]);
            bb[3] = *reinterpret_cast<const unsigned long long*>(&Bs[kk][tx * 8 + 6]);
            #pragma unroll
            for (int i = 0; i < 8; i++) {
                unsigned long long aa;
                asm("mov.b64 %0, {%1, %1};" : "=l"(aa) : "r"(__float_as_uint(a[i])));
                #pragma unroll
                for (int j = 0; j < 4; j++)
                    asm("fma.rn.f32x2 %0, %1, %2, %0;"
                        : "+l"(acc2[i][j]) : "l"(aa), "l"(bb[j]));
            }
        }

        __syncthreads();
    }

    // ---- Epilogue: unpack, + bias, relu, store ----
    #pragma unroll
    for (int i = 0; i < 8; i++) {
        const int n = block_row + ty * 8 + i;
        if (n >= N_NODES) break;
        float r[8];
        #pragma unroll
        for (int j = 0; j < 4; j++) {
            unsigned int lo, hi;
            asm("mov.b64 {%0, %1}, %2;" : "=r"(lo), "=r"(hi) : "l"(acc2[i][j]));
            r[j * 2 + 0] = __uint_as_float(lo);
            r[j * 2 + 1] = __uint_as_float(hi);
        }
        #pragma unroll
        for (int j4 = 0; j4 < 2; j4++) {
            const int col = tx * 8 + j4 * 4;
            const float4 bv = *reinterpret_cast<const float4*>(bias + col);
            float4 o;
            o.x = fmaxf(r[j4 * 4 + 0] + bv.x, 0.f);
            o.y = fmaxf(r[j4 * 4 + 1] + bv.y, 0.f);
            o.z = fmaxf(r[j4 * 4 + 2] + bv.z, 0.f);
            o.w = fmaxf(r[j4 * 4 + 3] + bv.w, 0.f);
            *reinterpret_cast<float4*>(out + (size_t)n * D_FEAT + col) = o;
        }
    }
}

// ---------------------------------------------------------------------------
// Launch
// ---------------------------------------------------------------------------
extern "C" void kernel_launch(void* const* d_in, const int* in_sizes, int n_in,
                              void* d_out, int out_size)
{
    const float* x       = (const float*)d_in[0];
    const int*   src_fwd = (const int*)  d_in[1];
    const int*   dst_fwd = (const int*)  d_in[2];
    const int*   src_bwd = (const int*)  d_in[3];
    const int*   dst_bwd = (const int*)  d_in[4];
    const float* rel_w   = (const float*)d_in[5];
    const float* loop_w  = (const float*)d_in[6];
    const float* h_bias  = (const float*)d_in[7];
    float* out = (float*)d_out;

    const int edge_blocks = (2 * E_EDGES + 255) / 256;   // 12500

    // CSR build: histogram -> scan -> counting-sort permute
    init_deg_kernel<<<(SEG + 1023) / 1024, 1024>>>();
    hist_kernel<<<edge_blocks, 256>>>(dst_fwd, dst_bwd);
    scan1_kernel<<<SCAN_BLK, 256>>>();
    scan2_kernel<<<1, 256>>>();
    scan3_kernel<<<SCAN_BLK, 256>>>();
    fill_kernel<<<edge_blocks, 256>>>(src_fwd, dst_fwd, src_bwd, dst_bwd);

    // Gather-aggregate (normalized rows written once)
    aggregate_kernel<<<SEG / 8, 256>>>(x);

    // Fused GEMM (f32x2 packed FMA) + bias + relu
    const int gemm_blocks = (N_NODES + BM - 1) / BM;
    gemm_kernel<<<gemm_blocks, 256>>>(x, rel_w, loop_w, h_bias, out);
}

// round 15
// speedup vs baseline: 1.7358x; 1.0454x over previous
#include <cuda_runtime.h>
#include <cuda_fp16.h>
#include <stdint.h>

#define N_NODES   100000
#define D_FEAT    128
#define E_EDGES   1600000
#define SEG       (2 * N_NODES)        // 200000 (rel,node) buckets
#define SCAN_BLK  196                  // 196 * 1024 >= SEG

// Scratch (__device__ globals — no allocation allowed)
__device__ float  g_agg[(size_t)SEG * D_FEAT];    // 102.4 MB
__device__ __half g_xh[(size_t)N_NODES * D_FEAT]; // 25.6 MB fp16 mirror of x
__device__ int    g_deg[SEG];
__device__ int    g_offs[SEG];
__device__ int    g_cursor[SEG];
__device__ int    g_bsum[SCAN_BLK];
__device__ int    g_sorted_src[2 * E_EDGES];      // 12.8 MB

// ---------------------------------------------------------------------------
// 0) fp16 mirror of x (read 51MB, write 25.6MB)
// ---------------------------------------------------------------------------
__global__ __launch_bounds__(256) void convert_kernel(const float* __restrict__ x) {
    const size_t total8 = (size_t)N_NODES * D_FEAT / 8;   // 1.6M
    const size_t stride = (size_t)gridDim.x * blockDim.x;
    for (size_t i = (size_t)blockIdx.x * blockDim.x + threadIdx.x; i < total8; i += stride) {
        const float4 a = reinterpret_cast<const float4*>(x)[i * 2 + 0];
        const float4 b = reinterpret_cast<const float4*>(x)[i * 2 + 1];
        __half2 h[4];
        h[0] = __floats2half2_rn(a.x, a.y);
        h[1] = __floats2half2_rn(a.z, a.w);
        h[2] = __floats2half2_rn(b.x, b.y);
        h[3] = __floats2half2_rn(b.z, b.w);
        reinterpret_cast<uint4*>(g_xh)[i] = *reinterpret_cast<uint4*>(h);
    }
}

// ---------------------------------------------------------------------------
// 1) zero degree histogram
// ---------------------------------------------------------------------------
__global__ void init_deg_kernel() {
    int i = blockIdx.x * blockDim.x + threadIdx.x;
    if (i < SEG) g_deg[i] = 0;
}

// ---------------------------------------------------------------------------
// 2) degree histogram
// ---------------------------------------------------------------------------
__global__ __launch_bounds__(256) void hist_kernel(
    const int* __restrict__ dst_f, const int* __restrict__ dst_b)
{
    int idx = blockIdx.x * blockDim.x + threadIdx.x;
    if (idx >= 2 * E_EDGES) return;
    int rel = (idx >= E_EDGES) ? 1 : 0;
    int e = idx - rel * E_EDGES;
    int d = __ldg(rel ? dst_b + e : dst_f + e);
    atomicAdd(&g_deg[rel * N_NODES + d], 1);
}

// ---------------------------------------------------------------------------
// 3) exclusive scan of g_deg -> g_offs (3-kernel scan)
// ---------------------------------------------------------------------------
__global__ __launch_bounds__(256) void scan1_kernel() {
    const int base = blockIdx.x * 1024;
    const int tid  = threadIdx.x;
    const int lane = tid & 31, w = tid >> 5;

    int v[4], sum = 0;
    #pragma unroll
    for (int j = 0; j < 4; j++) {
        int idx = base + tid * 4 + j;
        v[j] = (idx < SEG) ? g_deg[idx] : 0;
        sum += v[j];
    }
    int inc = sum;
    #pragma unroll
    for (int d = 1; d < 32; d <<= 1) {
        int t = __shfl_up_sync(0xffffffffu, inc, d);
        if (lane >= d) inc += t;
    }
    __shared__ int wsum[8];
    if (lane == 31) wsum[w] = inc;
    __syncthreads();
    if (w == 0 && lane < 8) {
        int t = wsum[lane];
        int s = t;
        #pragma unroll
        for (int d = 1; d < 8; d <<= 1) {
            int u = __shfl_up_sync(0xffu, s, d);
            if (lane >= d) s += u;
        }
        wsum[lane] = s - t;
    }
    __syncthreads();
    int excl = (inc - sum) + wsum[w];
    int run = excl;
    #pragma unroll
    for (int j = 0; j < 4; j++) {
        int idx = base + tid * 4 + j;
        if (idx < SEG) g_offs[idx] = run;
        run += v[j];
    }
    if (tid == 255) g_bsum[blockIdx.x] = excl + sum;
}

__global__ __launch_bounds__(256) void scan2_kernel() {
    const int tid = threadIdx.x;
    const int lane = tid & 31, w = tid >> 5;
    int v = (tid < SCAN_BLK) ? g_bsum[tid] : 0;
    int inc = v;
    #pragma unroll
    for (int d = 1; d < 32; d <<= 1) {
        int t = __shfl_up_sync(0xffffffffu, inc, d);
        if (lane >= d) inc += t;
    }
    __shared__ int wsum[8];
    if (lane == 31) wsum[w] = inc;
    __syncthreads();
    if (w == 0 && lane < 8) {
        int t = wsum[lane];
        int s = t;
        #pragma unroll
        for (int d = 1; d < 8; d <<= 1) {
            int u = __shfl_up_sync(0xffu, s, d);
            if (lane >= d) s += u;
        }
        wsum[lane] = s - t;
    }
    __syncthreads();
    if (tid < SCAN_BLK) g_bsum[tid] = (inc - v) + wsum[w];
}

__global__ __launch_bounds__(256) void scan3_kernel() {
    const int base = blockIdx.x * 1024;
    const int add = g_bsum[blockIdx.x];
    #pragma unroll
    for (int j = 0; j < 4; j++) {
        int idx = base + threadIdx.x * 4 + j;
        if (idx < SEG) {
            int o = g_offs[idx] + add;
            g_offs[idx] = o;
            g_cursor[idx] = o;
        }
    }
}

// ---------------------------------------------------------------------------
// 4) counting-sort fill: sorted_src grouped by (rel,dst)
// ---------------------------------------------------------------------------
__global__ __launch_bounds__(256) void fill_kernel(
    const int* __restrict__ src_f, const int* __restrict__ dst_f,
    const int* __restrict__ src_b, const int* __restrict__ dst_b)
{
    int idx = blockIdx.x * blockDim.x + threadIdx.x;
    if (idx >= 2 * E_EDGES) return;
    int rel = (idx >= E_EDGES) ? 1 : 0;
    int e = idx - rel * E_EDGES;
    int d = __ldg(rel ? dst_b + e : dst_f + e);
    int s = __ldg(rel ? src_b + e : src_f + e);
    int pos = atomicAdd(&g_cursor[rel * N_NODES + d], 1);
    g_sorted_src[pos] = s;
}

// ---------------------------------------------------------------------------
// 5) gather-aggregate (fp16 gather, fp32 accumulate): one warp per (rel,node).
//    Each lane loads 8B (4 halves) of the 256B fp16 row. Normalize, write
//    the fp32 agg row once.
// ---------------------------------------------------------------------------
__global__ __launch_bounds__(256) void aggregate_kernel() {
    const int wi = (blockIdx.x * blockDim.x + threadIdx.x) >> 5;   // bucket
    const int lane = threadIdx.x & 31;
    if (wi >= SEG) return;

    const int beg = g_offs[wi];
    const int dg  = g_deg[wi];

    float acc[4] = {0.f, 0.f, 0.f, 0.f};

    const uint2* __restrict__ xh = reinterpret_cast<const uint2*>(g_xh);

    for (int k0 = 0; k0 < dg; k0 += 32) {
        const int cnt = min(32, dg - k0);
        const int sid = (lane < cnt) ? __ldg(g_sorted_src + beg + k0 + lane) : 0;
        int j = 0;
        for (; j + 3 < cnt; j += 4) {
            const int s0 = __shfl_sync(0xffffffffu, sid, j + 0);
            const int s1 = __shfl_sync(0xffffffffu, sid, j + 1);
            const int s2 = __shfl_sync(0xffffffffu, sid, j + 2);
            const int s3 = __shfl_sync(0xffffffffu, sid, j + 3);
            const uint2 u0 = __ldg(xh + (size_t)s0 * 32 + lane);
            const uint2 u1 = __ldg(xh + (size_t)s1 * 32 + lane);
            const uint2 u2 = __ldg(xh + (size_t)s2 * 32 + lane);
            const uint2 u3 = __ldg(xh + (size_t)s3 * 32 + lane);
            #pragma unroll
            for (int q = 0; q < 4; q++) {
                const uint2 u = (q == 0) ? u0 : (q == 1) ? u1 : (q == 2) ? u2 : u3;
                const float2 f0 = __half22float2(*reinterpret_cast<const __half2*>(&u.x));
                const float2 f1 = __half22float2(*reinterpret_cast<const __half2*>(&u.y));
                acc[0] += f0.x; acc[1] += f0.y; acc[2] += f1.x; acc[3] += f1.y;
            }
        }
        for (; j < cnt; j++) {
            const int s0 = __shfl_sync(0xffffffffu, sid, j);
            const uint2 u = __ldg(xh + (size_t)s0 * 32 + lane);
            const float2 f0 = __half22float2(*reinterpret_cast<const __half2*>(&u.x));
            const float2 f1 = __half22float2(*reinterpret_cast<const __half2*>(&u.y));
            acc[0] += f0.x; acc[1] += f0.y; acc[2] += f1.x; acc[3] += f1.y;
        }
    }

    const float inv = 1.0f / (float)(dg > 1 ? dg : 1);
    float4 r;
    r.x = acc[0] * inv; r.y = acc[1] * inv;
    r.z = acc[2] * inv; r.w = acc[3] * inv;
    reinterpret_cast<float4*>(g_agg + (size_t)wi * D_FEAT)[lane] = r;
}

// ---------------------------------------------------------------------------
// 6) Fused GEMM with packed fp32x2 FMA:
//    out = relu( [agg0 | agg1 | x] @ [W0 ; W1 ; L] + bias )
// ---------------------------------------------------------------------------
#define BM 128
#define BN 128
#define BK 16

__global__ __launch_bounds__(256) void gemm_kernel(
    const float* __restrict__ x,
    const float* __restrict__ relw,    // [2,128,128]
    const float* __restrict__ loopw,   // [128,128]
    const float* __restrict__ bias,    // [128]
    float* __restrict__ out)
{
    __shared__ float As[BK][BM + 4];
    __shared__ float Bs[BK][BN];

    const int tid = threadIdx.x;
    const int tx = tid & 15;
    const int ty = tid >> 4;
    const int block_row = blockIdx.x * BM;

    unsigned long long acc2[8][4];
    #pragma unroll
    for (int i = 0; i < 8; i++)
        #pragma unroll
        for (int j = 0; j < 4; j++)
            acc2[i][j] = 0ull;

    for (int k0 = 0; k0 < 384; k0 += BK) {
        const int region = k0 >> 7;
        const int kk0 = k0 & 127;

        #pragma unroll
        for (int l = 0; l < 2; l++) {
            const int idx = tid + l * 256;
            const int row = idx >> 2;
            const int c4  = idx & 3;
            const int n = block_row + row;
            float4 v = make_float4(0.f, 0.f, 0.f, 0.f);
            if (n < N_NODES) {
                const float* base = (region < 2)
                    ? (g_agg + ((size_t)region * N_NODES + n) * D_FEAT + kk0 + c4 * 4)
                    : (x + (size_t)n * D_FEAT + kk0 + c4 * 4);
                v = *reinterpret_cast<const float4*>(base);
            }
            const int kb = c4 * 4;
            As[kb + 0][row] = v.x;
            As[kb + 1][row] = v.y;
            As[kb + 2][row] = v.z;
            As[kb + 3][row] = v.w;
        }

        #pragma unroll
        for (int l = 0; l < 2; l++) {
            const int idx = tid + l * 256;
            const int brow = idx >> 5;
            const int bc4  = idx & 31;
            const int k = k0 + brow;
            const float* src = (k < 256)
                ? (relw + (size_t)k * D_FEAT + bc4 * 4)
                : (loopw + (size_t)(k - 256) * D_FEAT + bc4 * 4);
            *reinterpret_cast<float4*>(&Bs[brow][bc4 * 4]) =
                *reinterpret_cast<const float4*>(src);
        }

        __syncthreads();

        #pragma unroll
        for (int kk = 0; kk < BK; kk++) {
            float a[8];
            *reinterpret_cast<float4*>(&a[0]) =
                *reinterpret_cast<const float4*>(&As[kk][ty * 8]);
            *reinterpret_cast<float4*>(&a[4]) =
                *reinterpret_cast<const float4*>(&As[kk][ty * 8 + 4]);
            unsigned long long bb[4];
            bb[0] = *reinterpret_cast<const unsigned long long*>(&Bs[kk][tx * 8 + 0]);
            bb[1] = *reinterpret_cast<const unsigned long long*>(&Bs[kk][tx * 8 + 2]);
            bb[2] = *reinterpret_cast<const unsigned long long*>(&Bs[kk][tx * 8 + 4]);
            bb[3] = *reinterpret_cast<const unsigned long long*>(&Bs[kk][tx * 8 + 6]);
            #pragma unroll
            for (int i = 0; i < 8; i++) {
                unsigned long long aa;
                asm("mov.b64 %0, {%1, %1};" : "=l"(aa) : "r"(__float_as_uint(a[i])));
                #pragma unroll
                for (int j = 0; j < 4; j++)
                    asm("fma.rn.f32x2 %0, %1, %2, %0;"
                        : "+l"(acc2[i][j]) : "l"(aa), "l"(bb[j]));
            }
        }

        __syncthreads();
    }

    #pragma unroll
    for (int i = 0; i < 8; i++) {
        const int n = block_row + ty * 8 + i;
        if (n >= N_NODES) break;
        float r[8];
        #pragma unroll
        for (int j = 0; j < 4; j++) {
            unsigned int lo, hi;
            asm("mov.b64 {%0, %1}, %2;" : "=r"(lo), "=r"(hi) : "l"(acc2[i][j]));
            r[j * 2 + 0] = __uint_as_float(lo);
            r[j * 2 + 1] = __uint_as_float(hi);
        }
        #pragma unroll
        for (int j4 = 0; j4 < 2; j4++) {
            const int col = tx * 8 + j4 * 4;
            const float4 bv = *reinterpret_cast<const float4*>(bias + col);
            float4 o;
            o.x = fmaxf(r[j4 * 4 + 0] + bv.x, 0.f);
            o.y = fmaxf(r[j4 * 4 + 1] + bv.y, 0.f);
            o.z = fmaxf(r[j4 * 4 + 2] + bv.z, 0.f);
            o.w = fmaxf(r[j4 * 4 + 3] + bv.w, 0.f);
            *reinterpret_cast<float4*>(out + (size_t)n * D_FEAT + col) = o;
        }
    }
}

// ---------------------------------------------------------------------------
// Launch
// ---------------------------------------------------------------------------
extern "C" void kernel_launch(void* const* d_in, const int* in_sizes, int n_in,
                              void* d_out, int out_size)
{
    const float* x       = (const float*)d_in[0];
    const int*   src_fwd = (const int*)  d_in[1];
    const int*   dst_fwd = (const int*)  d_in[2];
    const int*   src_bwd = (const int*)  d_in[3];
    const int*   dst_bwd = (const int*)  d_in[4];
    const float* rel_w   = (const float*)d_in[5];
    const float* loop_w  = (const float*)d_in[6];
    const float* h_bias  = (const float*)d_in[7];
    float* out = (float*)d_out;

    const int edge_blocks = (2 * E_EDGES + 255) / 256;   // 12500

    // fp16 mirror of x
    convert_kernel<<<2048, 256>>>(x);

    // CSR build: histogram -> scan -> counting-sort permute
    init_deg_kernel<<<(SEG + 1023) / 1024, 1024>>>();
    hist_kernel<<<edge_blocks, 256>>>(dst_fwd, dst_bwd);
    scan1_kernel<<<SCAN_BLK, 256>>>();
    scan2_kernel<<<1, 256>>>();
    scan3_kernel<<<SCAN_BLK, 256>>>();
    fill_kernel<<<edge_blocks, 256>>>(src_fwd, dst_fwd, src_bwd, dst_bwd);

    // Gather-aggregate (fp16 gather, fp32 accumulate, normalized rows)
    aggregate_kernel<<<SEG / 8, 256>>>();

    // Fused GEMM (f32x2 packed FMA) + bias + relu
    const int gemm_blocks = (N_NODES + BM - 1) / BM;
    gemm_kernel<<<gemm_blocks, 256>>>(x, rel_w, loop_w, h_bias, out);
}

// round 16
// speedup vs baseline: 3.2785x; 1.8887x over previous
#include <cuda_runtime.h>
#include <cuda_fp16.h>
#include <stdint.h>

#define N_NODES   100000
#define D_FEAT    128
#define E_EDGES   1600000
#define SEG       (2 * N_NODES)        // 200000 (rel,node) buckets
#define SCAN_BLK  196                  // 196 * 1024 >= SEG

// Scratch (__device__ globals — no allocation allowed)
__device__ __half g_aggh[(size_t)SEG * D_FEAT];   // 51.2 MB fp16 aggregates
__device__ __half g_xh[(size_t)N_NODES * D_FEAT]; // 25.6 MB fp16 mirror of x
__device__ __half g_wh[384 * D_FEAT];             // fp16 weights [W0;W1;L]
__device__ int    g_deg[SEG];
__device__ int    g_offs[SEG];
__device__ int    g_cursor[SEG];
__device__ int    g_bsum[SCAN_BLK];
__device__ int    g_sorted_src[2 * E_EDGES];      // 12.8 MB

// ---------------------------------------------------------------------------
// 0a) fp16 mirror of x
// ---------------------------------------------------------------------------
__global__ __launch_bounds__(256) void convert_kernel(const float* __restrict__ x) {
    const size_t total8 = (size_t)N_NODES * D_FEAT / 8;
    const size_t stride = (size_t)gridDim.x * blockDim.x;
    for (size_t i = (size_t)blockIdx.x * blockDim.x + threadIdx.x; i < total8; i += stride) {
        const float4 a = reinterpret_cast<const float4*>(x)[i * 2 + 0];
        const float4 b = reinterpret_cast<const float4*>(x)[i * 2 + 1];
        __half2 h[4];
        h[0] = __floats2half2_rn(a.x, a.y);
        h[1] = __floats2half2_rn(a.z, a.w);
        h[2] = __floats2half2_rn(b.x, b.y);
        h[3] = __floats2half2_rn(b.z, b.w);
        reinterpret_cast<uint4*>(g_xh)[i] = *reinterpret_cast<uint4*>(h);
    }
}

// 0b) fp16 weights: rows 0..255 = rel_weight, rows 256..383 = loop_weight
__global__ __launch_bounds__(256) void convert_w_kernel(
    const float* __restrict__ relw, const float* __restrict__ loopw)
{
    int i = blockIdx.x * blockDim.x + threadIdx.x;   // over 384*128/2 = 24576 pairs
    if (i >= 384 * D_FEAT / 2) return;
    const int elem = i * 2;
    const float2 v = (elem < 256 * D_FEAT)
        ? *reinterpret_cast<const float2*>(relw + elem)
        : *reinterpret_cast<const float2*>(loopw + (elem - 256 * D_FEAT));
    reinterpret_cast<__half2*>(g_wh)[i] = __floats2half2_rn(v.x, v.y);
}

// ---------------------------------------------------------------------------
// 1) zero degree histogram
// ---------------------------------------------------------------------------
__global__ void init_deg_kernel() {
    int i = blockIdx.x * blockDim.x + threadIdx.x;
    if (i < SEG) g_deg[i] = 0;
}

// ---------------------------------------------------------------------------
// 2) degree histogram
// ---------------------------------------------------------------------------
__global__ __launch_bounds__(256) void hist_kernel(
    const int* __restrict__ dst_f, const int* __restrict__ dst_b)
{
    int idx = blockIdx.x * blockDim.x + threadIdx.x;
    if (idx >= 2 * E_EDGES) return;
    int rel = (idx >= E_EDGES) ? 1 : 0;
    int e = idx - rel * E_EDGES;
    int d = __ldg(rel ? dst_b + e : dst_f + e);
    atomicAdd(&g_deg[rel * N_NODES + d], 1);
}

// ---------------------------------------------------------------------------
// 3) exclusive scan of g_deg -> g_offs
// ---------------------------------------------------------------------------
__global__ __launch_bounds__(256) void scan1_kernel() {
    const int base = blockIdx.x * 1024;
    const int tid  = threadIdx.x;
    const int lane = tid & 31, w = tid >> 5;

    int v[4], sum = 0;
    #pragma unroll
    for (int j = 0; j < 4; j++) {
        int idx = base + tid * 4 + j;
        v[j] = (idx < SEG) ? g_deg[idx] : 0;
        sum += v[j];
    }
    int inc = sum;
    #pragma unroll
    for (int d = 1; d < 32; d <<= 1) {
        int t = __shfl_up_sync(0xffffffffu, inc, d);
        if (lane >= d) inc += t;
    }
    __shared__ int wsum[8];
    if (lane == 31) wsum[w] = inc;
    __syncthreads();
    if (w == 0 && lane < 8) {
        int t = wsum[lane];
        int s = t;
        #pragma unroll
        for (int d = 1; d < 8; d <<= 1) {
            int u = __shfl_up_sync(0xffu, s, d);
            if (lane >= d) s += u;
        }
        wsum[lane] = s - t;
    }
    __syncthreads();
    int excl = (inc - sum) + wsum[w];
    int run = excl;
    #pragma unroll
    for (int j = 0; j < 4; j++) {
        int idx = base + tid * 4 + j;
        if (idx < SEG) g_offs[idx] = run;
        run += v[j];
    }
    if (tid == 255) g_bsum[blockIdx.x] = excl + sum;
}

__global__ __launch_bounds__(256) void scan2_kernel() {
    const int tid = threadIdx.x;
    const int lane = tid & 31, w = tid >> 5;
    int v = (tid < SCAN_BLK) ? g_bsum[tid] : 0;
    int inc = v;
    #pragma unroll
    for (int d = 1; d < 32; d <<= 1) {
        int t = __shfl_up_sync(0xffffffffu, inc, d);
        if (lane >= d) inc += t;
    }
    __shared__ int wsum[8];
    if (lane == 31) wsum[w] = inc;
    __syncthreads();
    if (w == 0 && lane < 8) {
        int t = wsum[lane];
        int s = t;
        #pragma unroll
        for (int d = 1; d < 8; d <<= 1) {
            int u = __shfl_up_sync(0xffu, s, d);
            if (lane >= d) s += u;
        }
        wsum[lane] = s - t;
    }
    __syncthreads();
    if (tid < SCAN_BLK) g_bsum[tid] = (inc - v) + wsum[w];
}

__global__ __launch_bounds__(256) void scan3_kernel() {
    const int base = blockIdx.x * 1024;
    const int add = g_bsum[blockIdx.x];
    #pragma unroll
    for (int j = 0; j < 4; j++) {
        int idx = base + threadIdx.x * 4 + j;
        if (idx < SEG) {
            int o = g_offs[idx] + add;
            g_offs[idx] = o;
            g_cursor[idx] = o;
        }
    }
}

// ---------------------------------------------------------------------------
// 4) counting-sort fill
// ---------------------------------------------------------------------------
__global__ __launch_bounds__(256) void fill_kernel(
    const int* __restrict__ src_f, const int* __restrict__ dst_f,
    const int* __restrict__ src_b, const int* __restrict__ dst_b)
{
    int idx = blockIdx.x * blockDim.x + threadIdx.x;
    if (idx >= 2 * E_EDGES) return;
    int rel = (idx >= E_EDGES) ? 1 : 0;
    int e = idx - rel * E_EDGES;
    int d = __ldg(rel ? dst_b + e : dst_f + e);
    int s = __ldg(rel ? src_b + e : src_f + e);
    int pos = atomicAdd(&g_cursor[rel * N_NODES + d], 1);
    g_sorted_src[pos] = s;
}

// ---------------------------------------------------------------------------
// 5) gather-aggregate (fp16 gather, fp32 accumulate, fp16 writeback)
// ---------------------------------------------------------------------------
__global__ __launch_bounds__(256) void aggregate_kernel() {
    const int wi = (blockIdx.x * blockDim.x + threadIdx.x) >> 5;
    const int lane = threadIdx.x & 31;
    if (wi >= SEG) return;

    const int beg = g_offs[wi];
    const int dg  = g_deg[wi];

    float acc[4] = {0.f, 0.f, 0.f, 0.f};
    const uint2* __restrict__ xh = reinterpret_cast<const uint2*>(g_xh);

    for (int k0 = 0; k0 < dg; k0 += 32) {
        const int cnt = min(32, dg - k0);
        const int sid = (lane < cnt) ? __ldg(g_sorted_src + beg + k0 + lane) : 0;
        int j = 0;
        for (; j + 3 < cnt; j += 4) {
            const int s0 = __shfl_sync(0xffffffffu, sid, j + 0);
            const int s1 = __shfl_sync(0xffffffffu, sid, j + 1);
            const int s2 = __shfl_sync(0xffffffffu, sid, j + 2);
            const int s3 = __shfl_sync(0xffffffffu, sid, j + 3);
            const uint2 u0 = __ldg(xh + (size_t)s0 * 32 + lane);
            const uint2 u1 = __ldg(xh + (size_t)s1 * 32 + lane);
            const uint2 u2 = __ldg(xh + (size_t)s2 * 32 + lane);
            const uint2 u3 = __ldg(xh + (size_t)s3 * 32 + lane);
            #pragma unroll
            for (int q = 0; q < 4; q++) {
                const uint2 u = (q == 0) ? u0 : (q == 1) ? u1 : (q == 2) ? u2 : u3;
                const float2 f0 = __half22float2(*reinterpret_cast<const __half2*>(&u.x));
                const float2 f1 = __half22float2(*reinterpret_cast<const __half2*>(&u.y));
                acc[0] += f0.x; acc[1] += f0.y; acc[2] += f1.x; acc[3] += f1.y;
            }
        }
        for (; j < cnt; j++) {
            const int s0 = __shfl_sync(0xffffffffu, sid, j);
            const uint2 u = __ldg(xh + (size_t)s0 * 32 + lane);
            const float2 f0 = __half22float2(*reinterpret_cast<const __half2*>(&u.x));
            const float2 f1 = __half22float2(*reinterpret_cast<const __half2*>(&u.y));
            acc[0] += f0.x; acc[1] += f0.y; acc[2] += f1.x; acc[3] += f1.y;
        }
    }

    const float inv = 1.0f / (float)(dg > 1 ? dg : 1);
    __half2 h0 = __floats2half2_rn(acc[0] * inv, acc[1] * inv);
    __half2 h1 = __floats2half2_rn(acc[2] * inv, acc[3] * inv);
    uint2 o;
    o.x = *reinterpret_cast<uint32_t*>(&h0);
    o.y = *reinterpret_cast<uint32_t*>(&h1);
    reinterpret_cast<uint2*>(g_aggh)[(size_t)wi * 32 + lane] = o;
}

// ---------------------------------------------------------------------------
// 6) HMMA fp16 GEMM (fp32 accumulate):
//    out = relu( [agg0 | agg1 | x]_fp16 @ Wh + bias )
//    128x128 block tile, BK=64, 8 warps each computing 64x32.
// ---------------------------------------------------------------------------
#define BM 128
#define BN 128
#define BK 64
#define A_PAD 8
#define B_PAD 8

__device__ __forceinline__ uint32_t smem_addr_u32(const void* p) {
    uint32_t a;
    asm("{ .reg .u64 t; cvta.to.shared.u64 t, %1; cvt.u32.u64 %0, t; }"
        : "=r"(a) : "l"(p));
    return a;
}

__global__ __launch_bounds__(256) void gemm_kernel(
    const float* __restrict__ bias,
    float* __restrict__ out)
{
    __shared__ __half As[BM][BK + A_PAD];   // 128 x 72 halves = 18 KB
    __shared__ __half Bs[BK][BN + B_PAD];   // 64 x 136 halves = 17 KB

    const int tid  = threadIdx.x;
    const int lane = tid & 31;
    const int wid  = tid >> 5;
    const int warp_m = wid & 1;     // 2 warps over M (64 rows each)
    const int warp_n = wid >> 1;    // 4 warps over N (32 cols each)
    const int block_row = blockIdx.x * BM;

    float c[4][4][4];
    #pragma unroll
    for (int mt = 0; mt < 4; mt++)
        #pragma unroll
        for (int nt = 0; nt < 4; nt++)
            #pragma unroll
            for (int r = 0; r < 4; r++)
                c[mt][nt][r] = 0.f;

    for (int k0 = 0; k0 < 384; k0 += BK) {
        const int region = k0 >> 7;          // 0,0,1,1,2,2 for k0=0..320
        const int kk0 = k0 & 127;            // 0 or 64

        // ---- A tile: 128 rows x 64 halves = 1024 uint4, 4 per thread ----
        #pragma unroll
        for (int l = 0; l < 4; l++) {
            const int idx = tid + l * 256;
            const int row = idx >> 3;        // 0..127
            const int c8  = idx & 7;         // uint4 col (8 halves each)
            const int n = block_row + row;
            uint4 v = make_uint4(0u, 0u, 0u, 0u);
            if (n < N_NODES) {
                const __half* base = (region < 2)
                    ? (g_aggh + ((size_t)region * N_NODES + n) * D_FEAT + kk0)
                    : (g_xh + (size_t)n * D_FEAT + kk0);
                v = *reinterpret_cast<const uint4*>(base + c8 * 8);
            }
            *reinterpret_cast<uint4*>(&As[row][c8 * 8]) = v;
        }

        // ---- B tile: 64 rows x 128 halves = 1024 uint4, 4 per thread ----
        #pragma unroll
        for (int l = 0; l < 4; l++) {
            const int idx = tid + l * 256;
            const int row = idx >> 4;        // 0..63
            const int c8  = idx & 15;
            *reinterpret_cast<uint4*>(&Bs[row][c8 * 8]) =
                *reinterpret_cast<const uint4*>(g_wh + (size_t)(k0 + row) * D_FEAT + c8 * 8);
        }

        __syncthreads();

        #pragma unroll
        for (int kk = 0; kk < BK; kk += 16) {
            // A fragments: 4 m-tiles of 16x16
            uint32_t a[4][4];
            #pragma unroll
            for (int mt = 0; mt < 4; mt++) {
                const int row = warp_m * 64 + mt * 16 + (lane & 15);
                const int col = kk + (lane >> 4) * 8;
                const uint32_t addr = smem_addr_u32(&As[row][col]);
                asm volatile(
                    "ldmatrix.sync.aligned.m8n8.x4.shared.b16 {%0,%1,%2,%3}, [%4];"
                    : "=r"(a[mt][0]), "=r"(a[mt][1]), "=r"(a[mt][2]), "=r"(a[mt][3])
                    : "r"(addr));
            }
            // B fragments: 4 n-tiles of 16x8 (row-major smem -> trans)
            uint32_t b[4][2];
            #pragma unroll
            for (int nt = 0; nt < 4; nt++) {
                const int row = kk + (lane & 15);
                const int col = warp_n * 32 + nt * 8;
                const uint32_t addr = smem_addr_u32(&Bs[row][col]);
                asm volatile(
                    "ldmatrix.sync.aligned.m8n8.x2.trans.shared.b16 {%0,%1}, [%2];"
                    : "=r"(b[nt][0]), "=r"(b[nt][1])
                    : "r"(addr));
            }
            #pragma unroll
            for (int mt = 0; mt < 4; mt++)
                #pragma unroll
                for (int nt = 0; nt < 4; nt++)
                    asm volatile(
                        "mma.sync.aligned.m16n8k16.row.col.f32.f16.f16.f32 "
                        "{%0,%1,%2,%3}, {%4,%5,%6,%7}, {%8,%9}, {%0,%1,%2,%3};"
                        : "+f"(c[mt][nt][0]), "+f"(c[mt][nt][1]),
                          "+f"(c[mt][nt][2]), "+f"(c[mt][nt][3])
                        : "r"(a[mt][0]), "r"(a[mt][1]), "r"(a[mt][2]), "r"(a[mt][3]),
                          "r"(b[nt][0]), "r"(b[nt][1]));
        }

        __syncthreads();
    }

    // ---- Epilogue: + bias, relu, store fp32 ----
    const int qrow = lane >> 2;          // 0..7
    const int qcol = (lane & 3) * 2;     // 0,2,4,6
    #pragma unroll
    for (int mt = 0; mt < 4; mt++) {
        #pragma unroll
        for (int nt = 0; nt < 4; nt++) {
            const int col = warp_n * 32 + nt * 8 + qcol;
            const float2 bv = *reinterpret_cast<const float2*>(bias + col);
            const int r0 = block_row + warp_m * 64 + mt * 16 + qrow;
            if (r0 < N_NODES) {
                float2 o;
                o.x = fmaxf(c[mt][nt][0] + bv.x, 0.f);
                o.y = fmaxf(c[mt][nt][1] + bv.y, 0.f);
                *reinterpret_cast<float2*>(out + (size_t)r0 * D_FEAT + col) = o;
            }
            const int r1 = r0 + 8;
            if (r1 < N_NODES) {
                float2 o;
                o.x = fmaxf(c[mt][nt][2] + bv.x, 0.f);
                o.y = fmaxf(c[mt][nt][3] + bv.y, 0.f);
                *reinterpret_cast<float2*>(out + (size_t)r1 * D_FEAT + col) = o;
            }
        }
    }
}

// ---------------------------------------------------------------------------
// Launch
// ---------------------------------------------------------------------------
extern "C" void kernel_launch(void* const* d_in, const int* in_sizes, int n_in,
                              void* d_out, int out_size)
{
    const float* x       = (const float*)d_in[0];
    const int*   src_fwd = (const int*)  d_in[1];
    const int*   dst_fwd = (const int*)  d_in[2];
    const int*   src_bwd = (const int*)  d_in[3];
    const int*   dst_bwd = (const int*)  d_in[4];
    const float* rel_w   = (const float*)d_in[5];
    const float* loop_w  = (const float*)d_in[6];
    const float* h_bias  = (const float*)d_in[7];
    float* out = (float*)d_out;

    const int edge_blocks = (2 * E_EDGES + 255) / 256;   // 12500

    // fp16 mirrors: x and weights
    convert_kernel<<<2048, 256>>>(x);
    convert_w_kernel<<<(384 * D_FEAT / 2 + 255) / 256, 256>>>(rel_w, loop_w);

    // CSR build: histogram -> scan -> counting-sort permute
    init_deg_kernel<<<(SEG + 1023) / 1024, 1024>>>();
    hist_kernel<<<edge_blocks, 256>>>(dst_fwd, dst_bwd);
    scan1_kernel<<<SCAN_BLK, 256>>>();
    scan2_kernel<<<1, 256>>>();
    scan3_kernel<<<SCAN_BLK, 256>>>();
    fill_kernel<<<edge_blocks, 256>>>(src_fwd, dst_fwd, src_bwd, dst_bwd);

    // Gather-aggregate (fp16 gather, fp32 accumulate, fp16 writeback)
    aggregate_kernel<<<SEG / 8, 256>>>();

    // HMMA fp16 GEMM + bias + relu
    const int gemm_blocks = (N_NODES + BM - 1) / BM;   // 782
    gemm_kernel<<<gemm_blocks, 256>>>(h_bias, out);
}

// round 17
// speedup vs baseline: 3.2814x; 1.0009x over previous
#include <cuda_runtime.h>
#include <cuda_fp16.h>
#include <stdint.h>

#define N_NODES   100000
#define D_FEAT    128
#define E_EDGES   1600000
#define SEG       (2 * N_NODES)        // 200000 (rel,node) buckets
#define SCAN_BLK  196                  // 196 * 1024 >= SEG

// Scratch (__device__ globals — no allocation allowed)
__device__ __half g_aggh[(size_t)SEG * D_FEAT];   // 51.2 MB fp16 aggregates
__device__ __half g_xh[(size_t)N_NODES * D_FEAT]; // 25.6 MB fp16 mirror of x
__device__ __half g_wh[384 * D_FEAT];             // fp16 weights [W0;W1;L]
__device__ int    g_deg[SEG];
__device__ int    g_offs[SEG];
__device__ int    g_cursor[SEG];
__device__ int    g_bsum[SCAN_BLK];
__device__ int    g_sorted_src[2 * E_EDGES];      // 12.8 MB

// ---------------------------------------------------------------------------
// 0a) fp16 mirror of x
// ---------------------------------------------------------------------------
__global__ __launch_bounds__(256) void convert_kernel(const float* __restrict__ x) {
    const size_t total8 = (size_t)N_NODES * D_FEAT / 8;
    const size_t stride = (size_t)gridDim.x * blockDim.x;
    for (size_t i = (size_t)blockIdx.x * blockDim.x + threadIdx.x; i < total8; i += stride) {
        const float4 a = reinterpret_cast<const float4*>(x)[i * 2 + 0];
        const float4 b = reinterpret_cast<const float4*>(x)[i * 2 + 1];
        __half2 h[4];
        h[0] = __floats2half2_rn(a.x, a.y);
        h[1] = __floats2half2_rn(a.z, a.w);
        h[2] = __floats2half2_rn(b.x, b.y);
        h[3] = __floats2half2_rn(b.z, b.w);
        reinterpret_cast<uint4*>(g_xh)[i] = *reinterpret_cast<uint4*>(h);
    }
}

// 0b) fp16 weights: rows 0..255 = rel_weight, rows 256..383 = loop_weight
__global__ __launch_bounds__(256) void convert_w_kernel(
    const float* __restrict__ relw, const float* __restrict__ loopw)
{
    int i = blockIdx.x * blockDim.x + threadIdx.x;   // over 384*128/2 = 24576 pairs
    if (i >= 384 * D_FEAT / 2) return;
    const int elem = i * 2;
    const float2 v = (elem < 256 * D_FEAT)
        ? *reinterpret_cast<const float2*>(relw + elem)
        : *reinterpret_cast<const float2*>(loopw + (elem - 256 * D_FEAT));
    reinterpret_cast<__half2*>(g_wh)[i] = __floats2half2_rn(v.x, v.y);
}

// ---------------------------------------------------------------------------
// 1) zero degree histogram
// ---------------------------------------------------------------------------
__global__ void init_deg_kernel() {
    int i = blockIdx.x * blockDim.x + threadIdx.x;
    if (i < SEG) g_deg[i] = 0;
}

// ---------------------------------------------------------------------------
// 2) degree histogram
// ---------------------------------------------------------------------------
__global__ __launch_bounds__(256) void hist_kernel(
    const int* __restrict__ dst_f, const int* __restrict__ dst_b)
{
    int idx = blockIdx.x * blockDim.x + threadIdx.x;
    if (idx >= 2 * E_EDGES) return;
    int rel = (idx >= E_EDGES) ? 1 : 0;
    int e = idx - rel * E_EDGES;
    int d = __ldg(rel ? dst_b + e : dst_f + e);
    atomicAdd(&g_deg[rel * N_NODES + d], 1);
}

// ---------------------------------------------------------------------------
// 3) exclusive scan of g_deg -> g_offs
// ---------------------------------------------------------------------------
__global__ __launch_bounds__(256) void scan1_kernel() {
    const int base = blockIdx.x * 1024;
    const int tid  = threadIdx.x;
    const int lane = tid & 31, w = tid >> 5;

    int v[4], sum = 0;
    #pragma unroll
    for (int j = 0; j < 4; j++) {
        int idx = base + tid * 4 + j;
        v[j] = (idx < SEG) ? g_deg[idx] : 0;
        sum += v[j];
    }
    int inc = sum;
    #pragma unroll
    for (int d = 1; d < 32; d <<= 1) {
        int t = __shfl_up_sync(0xffffffffu, inc, d);
        if (lane >= d) inc += t;
    }
    __shared__ int wsum[8];
    if (lane == 31) wsum[w] = inc;
    __syncthreads();
    if (w == 0 && lane < 8) {
        int t = wsum[lane];
        int s = t;
        #pragma unroll
        for (int d = 1; d < 8; d <<= 1) {
            int u = __shfl_up_sync(0xffu, s, d);
            if (lane >= d) s += u;
        }
        wsum[lane] = s - t;
    }
    __syncthreads();
    int excl = (inc - sum) + wsum[w];
    int run = excl;
    #pragma unroll
    for (int j = 0; j < 4; j++) {
        int idx = base + tid * 4 + j;
        if (idx < SEG) g_offs[idx] = run;
        run += v[j];
    }
    if (tid == 255) g_bsum[blockIdx.x] = excl + sum;
}

__global__ __launch_bounds__(256) void scan2_kernel() {
    const int tid = threadIdx.x;
    const int lane = tid & 31, w = tid >> 5;
    int v = (tid < SCAN_BLK) ? g_bsum[tid] : 0;
    int inc = v;
    #pragma unroll
    for (int d = 1; d < 32; d <<= 1) {
        int t = __shfl_up_sync(0xffffffffu, inc, d);
        if (lane >= d) inc += t;
    }
    __shared__ int wsum[8];
    if (lane == 31) wsum[w] = inc;
    __syncthreads();
    if (w == 0 && lane < 8) {
        int t = wsum[lane];
        int s = t;
        #pragma unroll
        for (int d = 1; d < 8; d <<= 1) {
            int u = __shfl_up_sync(0xffu, s, d);
            if (lane >= d) s += u;
        }
        wsum[lane] = s - t;
    }
    __syncthreads();
    if (tid < SCAN_BLK) g_bsum[tid] = (inc - v) + wsum[w];
}

__global__ __launch_bounds__(256) void scan3_kernel() {
    const int base = blockIdx.x * 1024;
    const int add = g_bsum[blockIdx.x];
    #pragma unroll
    for (int j = 0; j < 4; j++) {
        int idx = base + threadIdx.x * 4 + j;
        if (idx < SEG) {
            int o = g_offs[idx] + add;
            g_offs[idx] = o;
            g_cursor[idx] = o;
        }
    }
}

// ---------------------------------------------------------------------------
// 4) counting-sort fill
// ---------------------------------------------------------------------------
__global__ __launch_bounds__(256) void fill_kernel(
    const int* __restrict__ src_f, const int* __restrict__ dst_f,
    const int* __restrict__ src_b, const int* __restrict__ dst_b)
{
    int idx = blockIdx.x * blockDim.x + threadIdx.x;
    if (idx >= 2 * E_EDGES) return;
    int rel = (idx >= E_EDGES) ? 1 : 0;
    int e = idx - rel * E_EDGES;
    int d = __ldg(rel ? dst_b + e : dst_f + e);
    int s = __ldg(rel ? src_b + e : src_f + e);
    int pos = atomicAdd(&g_cursor[rel * N_NODES + d], 1);
    g_sorted_src[pos] = s;
}

// ---------------------------------------------------------------------------
// 5) gather-aggregate (fp16 gather, fp32 accumulate, fp16 writeback)
// ---------------------------------------------------------------------------
__global__ __launch_bounds__(256) void aggregate_kernel() {
    const int wi = (blockIdx.x * blockDim.x + threadIdx.x) >> 5;
    const int lane = threadIdx.x & 31;
    if (wi >= SEG) return;

    const int beg = g_offs[wi];
    const int dg  = g_deg[wi];

    float acc[4] = {0.f, 0.f, 0.f, 0.f};
    const uint2* __restrict__ xh = reinterpret_cast<const uint2*>(g_xh);

    for (int k0 = 0; k0 < dg; k0 += 32) {
        const int cnt = min(32, dg - k0);
        const int sid = (lane < cnt) ? __ldg(g_sorted_src + beg + k0 + lane) : 0;
        int j = 0;
        for (; j + 3 < cnt; j += 4) {
            const int s0 = __shfl_sync(0xffffffffu, sid, j + 0);
            const int s1 = __shfl_sync(0xffffffffu, sid, j + 1);
            const int s2 = __shfl_sync(0xffffffffu, sid, j + 2);
            const int s3 = __shfl_sync(0xffffffffu, sid, j + 3);
            const uint2 u0 = __ldg(xh + (size_t)s0 * 32 + lane);
            const uint2 u1 = __ldg(xh + (size_t)s1 * 32 + lane);
            const uint2 u2 = __ldg(xh + (size_t)s2 * 32 + lane);
            const uint2 u3 = __ldg(xh + (size_t)s3 * 32 + lane);
            #pragma unroll
            for (int q = 0; q < 4; q++) {
                const uint2 u = (q == 0) ? u0 : (q == 1) ? u1 : (q == 2) ? u2 : u3;
                const float2 f0 = __half22float2(*reinterpret_cast<const __half2*>(&u.x));
                const float2 f1 = __half22float2(*reinterpret_cast<const __half2*>(&u.y));
                acc[0] += f0.x; acc[1] += f0.y; acc[2] += f1.x; acc[3] += f1.y;
            }
        }
        for (; j < cnt; j++) {
            const int s0 = __shfl_sync(0xffffffffu, sid, j);
            const uint2 u = __ldg(xh + (size_t)s0 * 32 + lane);
            const float2 f0 = __half22float2(*reinterpret_cast<const __half2*>(&u.x));
            const float2 f1 = __half22float2(*reinterpret_cast<const __half2*>(&u.y));
            acc[0] += f0.x; acc[1] += f0.y; acc[2] += f1.x; acc[3] += f1.y;
        }
    }

    const float inv = 1.0f / (float)(dg > 1 ? dg : 1);
    __half2 h0 = __floats2half2_rn(acc[0] * inv, acc[1] * inv);
    __half2 h1 = __floats2half2_rn(acc[2] * inv, acc[3] * inv);
    uint2 o;
    o.x = *reinterpret_cast<uint32_t*>(&h0);
    o.y = *reinterpret_cast<uint32_t*>(&h1);
    reinterpret_cast<uint2*>(g_aggh)[(size_t)wi * 32 + lane] = o;
}

// ---------------------------------------------------------------------------
// 6) HMMA fp16 GEMM (fp32 accumulate):
//    out = relu( [agg0 | agg1 | x]_fp16 @ Wh + bias )
//    128x128 block tile, BK=64, 8 warps each computing 64x32.
// ---------------------------------------------------------------------------
#define BM 128
#define BN 128
#define BK 64
#define A_PAD 8
#define B_PAD 8

__device__ __forceinline__ uint32_t smem_addr_u32(const void* p) {
    uint32_t a;
    asm("{ .reg .u64 t; cvta.to.shared.u64 t, %1; cvt.u32.u64 %0, t; }"
        : "=r"(a) : "l"(p));
    return a;
}

__global__ __launch_bounds__(256) void gemm_kernel(
    const float* __restrict__ bias,
    float* __restrict__ out)
{
    __shared__ __half As[BM][BK + A_PAD];   // 128 x 72 halves = 18 KB
    __shared__ __half Bs[BK][BN + B_PAD];   // 64 x 136 halves = 17 KB

    const int tid  = threadIdx.x;
    const int lane = tid & 31;
    const int wid  = tid >> 5;
    const int warp_m = wid & 1;     // 2 warps over M (64 rows each)
    const int warp_n = wid >> 1;    // 4 warps over N (32 cols each)
    const int block_row = blockIdx.x * BM;

    float c[4][4][4];
    #pragma unroll
    for (int mt = 0; mt < 4; mt++)
        #pragma unroll
        for (int nt = 0; nt < 4; nt++)
            #pragma unroll
            for (int r = 0; r < 4; r++)
                c[mt][nt][r] = 0.f;

    for (int k0 = 0; k0 < 384; k0 += BK) {
        const int region = k0 >> 7;          // 0,0,1,1,2,2 for k0=0..320
        const int kk0 = k0 & 127;            // 0 or 64

        // ---- A tile: 128 rows x 64 halves = 1024 uint4, 4 per thread ----
        #pragma unroll
        for (int l = 0; l < 4; l++) {
            const int idx = tid + l * 256;
            const int row = idx >> 3;        // 0..127
            const int c8  = idx & 7;         // uint4 col (8 halves each)
            const int n = block_row + row;
            uint4 v = make_uint4(0u, 0u, 0u, 0u);
            if (n < N_NODES) {
                const __half* base = (region < 2)
                    ? (g_aggh + ((size_t)region * N_NODES + n) * D_FEAT + kk0)
                    : (g_xh + (size_t)n * D_FEAT + kk0);
                v = *reinterpret_cast<const uint4*>(base + c8 * 8);
            }
            *reinterpret_cast<uint4*>(&As[row][c8 * 8]) = v;
        }

        // ---- B tile: 64 rows x 128 halves = 1024 uint4, 4 per thread ----
        #pragma unroll
        for (int l = 0; l < 4; l++) {
            const int idx = tid + l * 256;
            const int row = idx >> 4;        // 0..63
            const int c8  = idx & 15;
            *reinterpret_cast<uint4*>(&Bs[row][c8 * 8]) =
                *reinterpret_cast<const uint4*>(g_wh + (size_t)(k0 + row) * D_FEAT + c8 * 8);
        }

        __syncthreads();

        #pragma unroll
        for (int kk = 0; kk < BK; kk += 16) {
            // A fragments: 4 m-tiles of 16x16
            uint32_t a[4][4];
            #pragma unroll
            for (int mt = 0; mt < 4; mt++) {
                const int row = warp_m * 64 + mt * 16 + (lane & 15);
                const int col = kk + (lane >> 4) * 8;
                const uint32_t addr = smem_addr_u32(&As[row][col]);
                asm volatile(
                    "ldmatrix.sync.aligned.m8n8.x4.shared.b16 {%0,%1,%2,%3}, [%4];"
                    : "=r"(a[mt][0]), "=r"(a[mt][1]), "=r"(a[mt][2]), "=r"(a[mt][3])
                    : "r"(addr));
            }
            // B fragments: 4 n-tiles of 16x8 (row-major smem -> trans)
            uint32_t b[4][2];
            #pragma unroll
            for (int nt = 0; nt < 4; nt++) {
                const int row = kk + (lane & 15);
                const int col = warp_n * 32 + nt * 8;
                const uint32_t addr = smem_addr_u32(&Bs[row][col]);
                asm volatile(
                    "ldmatrix.sync.aligned.m8n8.x2.trans.shared.b16 {%0,%1}, [%2];"
                    : "=r"(b[nt][0]), "=r"(b[nt][1])
                    : "r"(addr));
            }
            #pragma unroll
            for (int mt = 0; mt < 4; mt++)
                #pragma unroll
                for (int nt = 0; nt < 4; nt++)
                    asm volatile(
                        "mma.sync.aligned.m16n8k16.row.col.f32.f16.f16.f32 "
                        "{%0,%1,%2,%3}, {%4,%5,%6,%7}, {%8,%9}, {%0,%1,%2,%3};"
                        : "+f"(c[mt][nt][0]), "+f"(c[mt][nt][1]),
                          "+f"(c[mt][nt][2]), "+f"(c[mt][nt][3])
                        : "r"(a[mt][0]), "r"(a[mt][1]), "r"(a[mt][2]), "r"(a[mt][3]),
                          "r"(b[nt][0]), "r"(b[nt][1]));
        }

        __syncthreads();
    }

    // ---- Epilogue: + bias, relu, store fp32 ----
    const int qrow = lane >> 2;          // 0..7
    const int qcol = (lane & 3) * 2;     // 0,2,4,6
    #pragma unroll
    for (int mt = 0; mt < 4; mt++) {
        #pragma unroll
        for (int nt = 0; nt < 4; nt++) {
            const int col = warp_n * 32 + nt * 8 + qcol;
            const float2 bv = *reinterpret_cast<const float2*>(bias + col);
            const int r0 = block_row + warp_m * 64 + mt * 16 + qrow;
            if (r0 < N_NODES) {
                float2 o;
                o.x = fmaxf(c[mt][nt][0] + bv.x, 0.f);
                o.y = fmaxf(c[mt][nt][1] + bv.y, 0.f);
                *reinterpret_cast<float2*>(out + (size_t)r0 * D_FEAT + col) = o;
            }
            const int r1 = r0 + 8;
            if (r1 < N_NODES) {
                float2 o;
                o.x = fmaxf(c[mt][nt][2] + bv.x, 0.f);
                o.y = fmaxf(c[mt][nt][3] + bv.y, 0.f);
                *reinterpret_cast<float2*>(out + (size_t)r1 * D_FEAT + col) = o;
            }
        }
    }
}

// ---------------------------------------------------------------------------
// Launch
// ---------------------------------------------------------------------------
extern "C" void kernel_launch(void* const* d_in, const int* in_sizes, int n_in,
                              void* d_out, int out_size)
{
    const float* x       = (const float*)d_in[0];
    const int*   src_fwd = (const int*)  d_in[1];
    const int*   dst_fwd = (const int*)  d_in[2];
    const int*   src_bwd = (const int*)  d_in[3];
    const int*   dst_bwd = (const int*)  d_in[4];
    const float* rel_w   = (const float*)d_in[5];
    const float* loop_w  = (const float*)d_in[6];
    const float* h_bias  = (const float*)d_in[7];
    float* out = (float*)d_out;

    const int edge_blocks = (2 * E_EDGES + 255) / 256;   // 12500

    // fp16 mirrors: x and weights
    convert_kernel<<<2048, 256>>>(x);
    convert_w_kernel<<<(384 * D_FEAT / 2 + 255) / 256, 256>>>(rel_w, loop_w);

    // CSR build: histogram -> scan -> counting-sort permute
    init_deg_kernel<<<(SEG + 1023) / 1024, 1024>>>();
    hist_kernel<<<edge_blocks, 256>>>(dst_fwd, dst_bwd);
    scan1_kernel<<<SCAN_BLK, 256>>>();
    scan2_kernel<<<1, 256>>>();
    scan3_kernel<<<SCAN_BLK, 256>>>();
    fill_kernel<<<edge_blocks, 256>>>(src_fwd, dst_fwd, src_bwd, dst_bwd);

    // Gather-aggregate (fp16 gather, fp32 accumulate, fp16 writeback)
    aggregate_kernel<<<SEG / 8, 256>>>();

    // HMMA fp16 GEMM + bias + relu
    const int gemm_blocks = (N_NODES + BM - 1) / BM;   // 782
    gemm_kernel<<<gemm_blocks, 256>>>(h_bias, out);
}